// round 4
// baseline (speedup 1.0000x reference)
#include <cuda_runtime.h>

// DynamicRouting: N=64, C=4, H=W=256 fp32. Single persistent fused kernel.
// Phase 1: per-block partial channel sums (ascending, L2-retained).
// Grid barrier (all 256 blocks co-resident by construction).
// Phase 2: gates -> folded coefs -> dense pass re-reading the SAME block-local
// slice in reverse chunk order (L2 recency), streaming stores for the output.

#define HW   65536
#define HW4  16384
#define NSMP 64

__device__ float    g_part[NSMP * 32];  // [n][k(0-3:x,4-7:y)][q(4)]
__device__ unsigned g_count = 0;        // barrier arrivals (reset each use)
__device__ unsigned g_flag  = 0;        // barrier epoch (monotonic across replays)

__global__ void __launch_bounds__(512, 2)
fused_kernel(const float* __restrict__ x, const float* __restrict__ y,
             float* __restrict__ out,
             const float* __restrict__ w_rf1, const float* __restrict__ b_rf1,
             const float* __restrict__ w_rf2, const float* __restrict__ b_rf2,
             const float* __restrict__ w_e1,  const float* __restrict__ b_e1,
             const float* __restrict__ w_e2,  const float* __restrict__ b_e2,
             const float* __restrict__ w_e3,  const float* __restrict__ b_e3,
             const float* __restrict__ w_e4,  const float* __restrict__ b_e4) {
    const int n = blockIdx.y;          // sample
    const int q = blockIdx.x;          // quarter of the plane
    const int t = threadIdx.x;
    const int base = q * 4096;         // float4 offset of this block's slice

    const float4* xb = (const float4*)(x + (size_t)n * 4 * HW);
    const float4* yb = (const float4*)(y + (size_t)n * 4 * HW);

    // ---------------- Phase 1: partial sums (ascending order) ----------------
    float s[8] = {0.f, 0.f, 0.f, 0.f, 0.f, 0.f, 0.f, 0.f};
    #pragma unroll
    for (int j = 0; j < 8; j++) {
        int pid = base + j * 512 + t;
        #pragma unroll
        for (int c = 0; c < 4; c++) {
            float4 vx = xb[(size_t)c * HW4 + pid];
            float4 vy = yb[(size_t)c * HW4 + pid];
            s[c]     += (vx.x + vx.y) + (vx.z + vx.w);
            s[4 + c] += (vy.x + vy.y) + (vy.z + vy.w);
        }
    }
    // block-reduce the 8 partials
    #pragma unroll
    for (int o = 16; o > 0; o >>= 1) {
        #pragma unroll
        for (int k = 0; k < 8; k++)
            s[k] += __shfl_down_sync(0xffffffffu, s[k], o);
    }
    __shared__ float ws[16][8];
    if ((t & 31) == 0) {
        #pragma unroll
        for (int k = 0; k < 8; k++) ws[t >> 5][k] = s[k];
    }
    __syncthreads();
    if (t < 8) {
        float acc = 0.f;
        #pragma unroll
        for (int w = 0; w < 16; w++) acc += ws[w][t];
        g_part[n * 32 + t * 4 + q] = acc;   // deterministic: one writer per slot
    }
    __syncthreads();

    // ---------------- Grid barrier (sense-reversing, replay-safe) ------------
    if (t == 0) {
        __threadfence();                                   // publish g_part
        unsigned v = atomicAdd(&g_flag, 0u);               // epoch before arrive
        unsigned a = atomicAdd(&g_count, 1u);
        if (a == NSMP * 4 - 1) {                           // last arriver
            atomicExch(&g_count, 0u);                      // reset for next use
            __threadfence();
            atomicExch(&g_flag, v + 1u);                   // release
        } else {
            while (atomicAdd(&g_flag, 0u) == v) __nanosleep(64);
        }
        __threadfence();                                   // acquire g_part
    }
    __syncthreads();

    // ---------------- Gates + folded coefficients ----------------------------
    __shared__ float mk[4];     // mx0, mx1, my0, my1
    __shared__ float cf[112];
    if (t == 0) {
        const float inv = 1.0f / (float)HW;
        float px[4], py[4];
        #pragma unroll
        for (int k = 0; k < 8; k++) {
            float a = 0.f;
            #pragma unroll
            for (int qq = 0; qq < 4; qq++) a += g_part[n * 32 + k * 4 + qq];
            if (k < 4) px[k] = a * inv; else py[k - 4] = a * inv;
        }
        float gx1[2], gy1[2];
        #pragma unroll
        for (int j = 0; j < 2; j++) {
            float ax = b_rf1[j], ay = b_rf1[j];
            #pragma unroll
            for (int c = 0; c < 4; c++) {
                ax += px[c] * w_rf1[j * 4 + c];
                ay += py[c] * w_rf1[j * 4 + c];
            }
            gx1[j] = ax; gy1[j] = ay;
        }
        float gx[2], gy[2];
        #pragma unroll
        for (int i = 0; i < 2; i++) {
            float ax = b_rf2[i], ay = b_rf2[i];
            #pragma unroll
            for (int j = 0; j < 2; j++) {
                ax += gx1[j] * w_rf2[i * 2 + j];
                ay += gy1[j] * w_rf2[i * 2 + j];
            }
            gx[i] = ax; gy[i] = ay;
        }
        mk[0] = gx[0] > 0.f ? 1.f : 0.f;
        mk[1] = gx[1] > 0.f ? 1.f : 0.f;
        mk[2] = gy[0] > 0.f ? 1.f : 0.f;
        mk[3] = gy[1] > 0.f ? 1.f : 0.f;
    }
    __syncthreads();
    if (t < 112) {
        float v;
        if      (t < 16)  v = mk[0] * w_e1[t];
        else if (t < 32)  v = mk[2] * w_e3[t - 16];
        else if (t < 36)  v = mk[0] * b_e1[t - 32] + mk[2] * b_e3[t - 32];
        else if (t < 68)  v = mk[1] * w_e2[t - 36];
        else if (t < 100) v = mk[3] * w_e4[t - 68];
        else              v = mk[1] * b_e2[t - 100] + mk[3] * b_e4[t - 100];
        cf[t] = v;
    }
    __syncthreads();

    // ---------------- Phase 2: dense pass, REVERSE chunk order ---------------
    float4* ox = (float4*)(out + (size_t)n * 4 * HW);
    float4* oy = (float4*)(out + (size_t)NSMP * 4 * HW + (size_t)n * 8 * HW);

    #pragma unroll 1
    for (int j = 7; j >= 0; j--) {
        int pid = base + j * 512 + t;

        float4 xv[4], yv[4];
        #pragma unroll
        for (int c = 0; c < 4; c++) {
            xv[c] = __ldcs(xb + (size_t)c * HW4 + pid);   // dead after use
            yv[c] = __ldcs(yb + (size_t)c * HW4 + pid);
        }

        #pragma unroll
        for (int o = 0; o < 4; o++) {
            float b = cf[32 + o];
            float4 acc = make_float4(b, b, b, b);
            #pragma unroll
            for (int c = 0; c < 4; c++) {
                float a1 = cf[o * 4 + c];
                float a2 = cf[16 + o * 4 + c];
                acc.x += a1 * xv[c].x + a2 * yv[c].x;
                acc.y += a1 * xv[c].y + a2 * yv[c].y;
                acc.z += a1 * xv[c].z + a2 * yv[c].z;
                acc.w += a1 * xv[c].w + a2 * yv[c].w;
            }
            __stcs(ox + (size_t)o * HW4 + pid, acc);      // evict-first write
        }
        #pragma unroll
        for (int o = 0; o < 8; o++) {
            float b = cf[100 + o];
            float4 acc = make_float4(b, b, b, b);
            #pragma unroll
            for (int c = 0; c < 4; c++) {
                float a1 = cf[36 + o * 4 + c];
                float a2 = cf[68 + o * 4 + c];
                acc.x += a1 * xv[c].x + a2 * yv[c].x;
                acc.y += a1 * xv[c].y + a2 * yv[c].y;
                acc.z += a1 * xv[c].z + a2 * yv[c].z;
                acc.w += a1 * xv[c].w + a2 * yv[c].w;
            }
            __stcs(oy + (size_t)o * HW4 + pid, acc);
        }
    }
}

// ---------------------------------------------------------------------------
extern "C" void kernel_launch(void* const* d_in, const int* in_sizes, int n_in,
                              void* d_out, int out_size) {
    const float* x = (const float*)d_in[0];
    const float* y = (const float*)d_in[1];

    dim3 grid(4, NSMP);   // 256 blocks, all co-resident (512 thr, 2 blk/SM)
    fused_kernel<<<grid, 512>>>(
        x, y, (float*)d_out,
        (const float*)d_in[2],  (const float*)d_in[3],
        (const float*)d_in[4],  (const float*)d_in[5],
        (const float*)d_in[6],  (const float*)d_in[7],
        (const float*)d_in[8],  (const float*)d_in[9],
        (const float*)d_in[10], (const float*)d_in[11],
        (const float*)d_in[12], (const float*)d_in[13]);
}